// round 7
// baseline (speedup 1.0000x reference)
#include <cuda_runtime.h>
#include <cuda_bf16.h>
#include <mma.h>
#include <cstdint>
#include <math.h>

using namespace nvcuda;

#define BB    128
#define SSQ   256
#define LLC   16
#define EMB   256
#define HID   512
#define NCLS  20
#define CEMB  64
#define CHID  128
#define NW    (BB*SSQ)        // 32768 words
#define DIM   384             // EMB + CHID
#define G3C   384             // 3*CHID
#define G3H   1536            // 3*HID
#define NBLK_W 128

// ---------------- scratch (__device__ globals, no allocation) ----------------
__device__ float g_cxw[(size_t)NW*LLC*G3C];       // char input projections
__device__ float g_charh[NW*CHID];                // char GRU final hidden (n = s*B+b)
__device__ float g_xw[(size_t)NW*G3H];            // word input projections
__device__ float g_hword[2*BB*HID];
__device__ float g_gruout[(size_t)NW*HID];
__device__ unsigned int g_barArrive;
__device__ unsigned int g_barPhase;
// split-bf16 weights (row-major [N][K])
__device__ __nv_bfloat16 g_BxwHi[G3H*DIM],  g_BxwLo[G3H*DIM];
__device__ __nv_bfloat16 g_BcxHi[G3C*CEMB], g_BcxLo[G3C*CEMB];
__device__ __nv_bfloat16 g_WhHi[G3C*CHID],  g_WhLo[G3C*CHID];   // char Wh
// split-bf16 gathered A matrices
__device__ __nv_bfloat16 g_AcH[(size_t)NW*LLC*CEMB], g_AcL[(size_t)NW*LLC*CEMB];
__device__ __nv_bfloat16 g_AxH[(size_t)NW*DIM],      g_AxL[(size_t)NW*DIM];

// ---------------- helpers ----------------
__device__ __forceinline__ void cvtf4(float4 v, uint2& hi, uint2& lo) {
    __nv_bfloat16 hx = __float2bfloat16(v.x), hy = __float2bfloat16(v.y);
    __nv_bfloat16 hz = __float2bfloat16(v.z), hw = __float2bfloat16(v.w);
    float lx = v.x - __bfloat162float(hx), ly = v.y - __bfloat162float(hy);
    float lz = v.z - __bfloat162float(hz), lw = v.w - __bfloat162float(hw);
    union { __nv_bfloat162 b; uint32_t u; } a0, a1, b0, b1;
    a0.b = __halves2bfloat162(hx, hy);  a1.b = __halves2bfloat162(hz, hw);
    b0.b = __halves2bfloat162(__float2bfloat16(lx), __float2bfloat16(ly));
    b1.b = __halves2bfloat162(__float2bfloat16(lz), __float2bfloat16(lw));
    hi = make_uint2(a0.u, a1.u);
    lo = make_uint2(b0.u, b1.u);
}

// ---------------- kernel P: weight prep ----------------
__global__ void k_prep(const float* __restrict__ cWh, const float* __restrict__ gWi,
                       const float* __restrict__ cWi) {
    int stride = gridDim.x * blockDim.x;
    int i0 = blockIdx.x * blockDim.x + threadIdx.x;
    for (int i = i0; i < G3C*CHID; i += stride) {
        float v = cWh[i];
        __nv_bfloat16 h = __float2bfloat16(v);
        g_WhHi[i] = h;
        g_WhLo[i] = __float2bfloat16(v - __bfloat162float(h));
    }
    for (int i = i0; i < G3H*DIM; i += stride) {
        float v = gWi[i];
        __nv_bfloat16 h = __float2bfloat16(v);
        g_BxwHi[i] = h;
        g_BxwLo[i] = __float2bfloat16(v - __bfloat162float(h));
    }
    for (int i = i0; i < G3C*CEMB; i += stride) {
        float v = cWi[i];
        __nv_bfloat16 h = __float2bfloat16(v);
        g_BcxHi[i] = h;
        g_BcxLo[i] = __float2bfloat16(v - __bfloat162float(h));
    }
}

// ---------------- gather A for char GEMM ----------------
__global__ __launch_bounds__(256)
void k_gatherA_c(const int* __restrict__ xc, const float* __restrict__ cembw) {
    const int r = blockIdx.x * 256 + threadIdx.x;
    const int c = xc[r];
    const float4* src = (const float4*)(cembw + (size_t)c * CEMB);
    uint2* dh = (uint2*)(g_AcH + (size_t)r * CEMB);
    uint2* dl = (uint2*)(g_AcL + (size_t)r * CEMB);
    #pragma unroll
    for (int i = 0; i < 16; i++) {
        uint2 hi, lo;
        cvtf4(src[i], hi, lo);
        dh[i] = hi; dl[i] = lo;
    }
}

// ---------------- gather A for word GEMM ----------------
__global__ __launch_bounds__(256)
void k_gatherA_x(const int* __restrict__ xtok, const float* __restrict__ embw) {
    const int warp = threadIdx.x >> 5, lane = threadIdx.x & 31;
    const int row = blockIdx.x * 8 + warp;
    const int tok = xtok[row];
    const int nidx = (row & 255) * 128 + (row >> 8);
    uint2* dh = (uint2*)(g_AxH + (size_t)row * DIM);
    uint2* dl = (uint2*)(g_AxL + (size_t)row * DIM);
    #pragma unroll
    for (int q = 0; q < 3; q++) {
        int k4 = q * 32 + lane;
        int k = k4 * 4;
        float4 v = (k < EMB)
            ? *(const float4*)(embw + (size_t)tok * EMB + k)
            : *(const float4*)(g_charh + (size_t)nidx * CHID + (k - EMB));
        uint2 hi, lo;
        cvtf4(v, hi, lo);
        dh[k4] = hi; dl[k4] = lo;
    }
}

// ---------------- wmma split-bf16 GEMM: C = A·B^T + bias ---------------------
#define GPAD 72
#define GSM_A  (128*GPAD)
#define GSM_B  (64*GPAD)
#define GEMM_SMEM ((2*GSM_A + 2*GSM_B) * 2)

__global__ __launch_bounds__(256)
void k_gemm(const __nv_bfloat16* __restrict__ Ah, const __nv_bfloat16* __restrict__ Al,
            const __nv_bfloat16* __restrict__ Bh, const __nv_bfloat16* __restrict__ Bl,
            const float* __restrict__ bias, float* __restrict__ C,
            int N, int K) {
    extern __shared__ char smraw[];
    __nv_bfloat16* sAh = (__nv_bfloat16*)smraw;
    __nv_bfloat16* sAl = sAh + GSM_A;
    __nv_bfloat16* sBh = sAl + GSM_A;
    __nv_bfloat16* sBl = sBh + GSM_B;
    float* sC = (float*)smraw;

    const int tid = threadIdx.x;
    const int warp = tid >> 5;
    const int wm = warp & 3, wn = warp >> 2;
    const int bm = blockIdx.y * 128, bn = blockIdx.x * 64;

    wmma::fragment<wmma::accumulator, 16, 16, 16, float> acc[2][2];
    #pragma unroll
    for (int i = 0; i < 2; i++)
        #pragma unroll
        for (int j = 0; j < 2; j++) wmma::fill_fragment(acc[i][j], 0.f);

    for (int k0 = 0; k0 < K; k0 += 64) {
        #pragma unroll
        for (int q = 0; q < 4; q++) {
            int j = tid * 4 + q;
            int r = j >> 3, c8 = j & 7;
            const uint4* sh = (const uint4*)(Ah + (size_t)(bm + r) * K + k0);
            const uint4* sl = (const uint4*)(Al + (size_t)(bm + r) * K + k0);
            *(uint4*)(sAh + r*GPAD + c8*8) = sh[c8];
            *(uint4*)(sAl + r*GPAD + c8*8) = sl[c8];
        }
        #pragma unroll
        for (int q = 0; q < 2; q++) {
            int j = tid * 2 + q;
            int r = j >> 3, c8 = j & 7;
            const uint4* sh = (const uint4*)(Bh + (size_t)(bn + r) * K + k0);
            const uint4* sl = (const uint4*)(Bl + (size_t)(bn + r) * K + k0);
            *(uint4*)(sBh + r*GPAD + c8*8) = sh[c8];
            *(uint4*)(sBl + r*GPAD + c8*8) = sl[c8];
        }
        __syncthreads();

        #pragma unroll
        for (int kk = 0; kk < 4; kk++) {
            wmma::fragment<wmma::matrix_a, 16, 16, 16, __nv_bfloat16, wmma::row_major> aH[2], aL[2];
            wmma::fragment<wmma::matrix_b, 16, 16, 16, __nv_bfloat16, wmma::col_major> bH[2], bL[2];
            #pragma unroll
            for (int mi = 0; mi < 2; mi++) {
                wmma::load_matrix_sync(aH[mi], sAh + (wm*32 + mi*16)*GPAD + kk*16, GPAD);
                wmma::load_matrix_sync(aL[mi], sAl + (wm*32 + mi*16)*GPAD + kk*16, GPAD);
            }
            #pragma unroll
            for (int ni = 0; ni < 2; ni++) {
                wmma::load_matrix_sync(bH[ni], sBh + (wn*32 + ni*16)*GPAD + kk*16, GPAD);
                wmma::load_matrix_sync(bL[ni], sBl + (wn*32 + ni*16)*GPAD + kk*16, GPAD);
            }
            #pragma unroll
            for (int mi = 0; mi < 2; mi++)
                #pragma unroll
                for (int ni = 0; ni < 2; ni++) {
                    wmma::mma_sync(acc[mi][ni], aH[mi], bH[ni], acc[mi][ni]);
                    wmma::mma_sync(acc[mi][ni], aH[mi], bL[ni], acc[mi][ni]);
                    wmma::mma_sync(acc[mi][ni], aL[mi], bH[ni], acc[mi][ni]);
                }
        }
        __syncthreads();
    }

    #pragma unroll
    for (int mi = 0; mi < 2; mi++)
        #pragma unroll
        for (int ni = 0; ni < 2; ni++)
            wmma::store_matrix_sync(sC + (wm*32 + mi*16)*68 + wn*32 + ni*16,
                                    acc[mi][ni], 68, wmma::mem_row_major);
    __syncthreads();
    #pragma unroll
    for (int q = 0; q < 8; q++) {
        int j = q * 256 + tid;
        int r = j >> 4, c4 = (j & 15) * 4;
        float4 v = *(float4*)(sC + r*68 + c4);
        float4 b = *(const float4*)(bias + bn + c4);
        v.x += b.x; v.y += b.y; v.z += b.z; v.w += b.w;
        *(float4*)(C + (size_t)(bm + r) * N + bn + c4) = v;
    }
}

// ---------------- kernel CR: char GRU recurrent (WMMA split-bf16) ------------
// Block: M=64 words, 512 threads (16 warps, 2m x 8n, warp tile 32x48).
// h kept in smem as split-bf16; Wh hi/lo streamed from global (L2-resident).
#define CRM   64
#define CR_HS 136                       // h row stride (bf16)
#define CR_PS 392                       // pre row stride (fp32)
#define CR_OFF_HLO  (CRM*CR_HS*2)       // 17408
#define CR_OFF_PRE  (2*CRM*CR_HS*2)     // 34816
#define CR_OFF_BH   (CR_OFF_PRE + CRM*CR_PS*4)   // 135168
#define CR_SMEM     (CR_OFF_BH + G3C*4)          // 136704

__global__ __launch_bounds__(512, 1)
void k_charrec(const float* __restrict__ cbh) {
    extern __shared__ char smraw[];
    __nv_bfloat16* hHi = (__nv_bfloat16*)smraw;
    __nv_bfloat16* hLo = (__nv_bfloat16*)(smraw + CR_OFF_HLO);
    float* pre = (float*)(smraw + CR_OFF_PRE);
    float* sbh = (float*)(smraw + CR_OFF_BH);
    const int tid = threadIdx.x;
    const int warp = tid >> 5;
    const int wm = warp & 1, wn = warp >> 1;
    const int m0 = wm * 32;
    const int n0 = wn * 48;
    const int w0 = blockIdx.x * CRM;

    // init h = 0, stage bh
    {
        uint32_t* hz = (uint32_t*)hHi;
        for (int i = tid; i < 2*CRM*CR_HS/2; i += 512) hz[i] = 0u;
        if (tid < G3C) sbh[tid] = cbh[tid];
    }
    __syncthreads();

    const int ju = tid & 127;        // gate-update column
    const int mb = tid >> 7;         // 0..3

    for (int t = 0; t < LLC; t++) {
        wmma::fragment<wmma::accumulator, 16, 16, 16, float> acc[2][3];
        #pragma unroll
        for (int mi = 0; mi < 2; mi++)
            #pragma unroll
            for (int ni = 0; ni < 3; ni++) wmma::fill_fragment(acc[mi][ni], 0.f);

        #pragma unroll
        for (int kk = 0; kk < 8; kk++) {
            wmma::fragment<wmma::matrix_a, 16, 16, 16, __nv_bfloat16, wmma::row_major> aH[2], aL[2];
            #pragma unroll
            for (int mi = 0; mi < 2; mi++) {
                wmma::load_matrix_sync(aH[mi], hHi + (m0 + mi*16)*CR_HS + kk*16, CR_HS);
                wmma::load_matrix_sync(aL[mi], hLo + (m0 + mi*16)*CR_HS + kk*16, CR_HS);
            }
            #pragma unroll
            for (int ni = 0; ni < 3; ni++) {
                const __nv_bfloat16* pbh = g_WhHi + (size_t)(n0 + ni*16)*CHID + kk*16;
                const __nv_bfloat16* pbl = g_WhLo + (size_t)(n0 + ni*16)*CHID + kk*16;
                wmma::fragment<wmma::matrix_b, 16, 16, 16, __nv_bfloat16, wmma::col_major> bH, bL;
                wmma::load_matrix_sync(bH, pbh, CHID);
                wmma::load_matrix_sync(bL, pbl, CHID);
                #pragma unroll
                for (int mi = 0; mi < 2; mi++) {
                    wmma::mma_sync(acc[mi][ni], aH[mi], bH, acc[mi][ni]);
                    wmma::mma_sync(acc[mi][ni], aH[mi], bL, acc[mi][ni]);
                    wmma::mma_sync(acc[mi][ni], aL[mi], bH, acc[mi][ni]);
                }
            }
        }
        #pragma unroll
        for (int mi = 0; mi < 2; mi++)
            #pragma unroll
            for (int ni = 0; ni < 3; ni++)
                wmma::store_matrix_sync(pre + (m0 + mi*16)*CR_PS + n0 + ni*16,
                                        acc[mi][ni], CR_PS, wmma::mem_row_major);
        __syncthreads();

        // gate update: each thread owns 16 (m, j) pairs
        #pragma unroll
        for (int q = 0; q < 16; q++) {
            int m = mb + q*4;
            float pR = pre[m*CR_PS + ju] + sbh[ju];
            float pZ = pre[m*CR_PS + CHID + ju] + sbh[CHID + ju];
            float pN = pre[m*CR_PS + 2*CHID + ju] + sbh[2*CHID + ju];
            size_t rr = ((size_t)(w0 + m)*LLC + t)*G3C;
            float xr = g_cxw[rr + ju];
            float xz = g_cxw[rr + CHID + ju];
            float xn = g_cxw[rr + 2*CHID + ju];
            float r  = 1.f / (1.f + expf(-(xr + pR)));
            float z  = 1.f / (1.f + expf(-(xz + pZ)));
            float nn = tanhf(xn + r*pN);
            float hp = __bfloat162float(hHi[m*CR_HS + ju]) + __bfloat162float(hLo[m*CR_HS + ju]);
            float hn = nn + z*(hp - nn);
            __nv_bfloat16 hh = __float2bfloat16(hn);
            hHi[m*CR_HS + ju] = hh;
            hLo[m*CR_HS + ju] = __float2bfloat16(hn - __bfloat162float(hh));
        }
        __syncthreads();
    }

    #pragma unroll
    for (int q = 0; q < 16; q++) {
        int m = mb + q*4;
        g_charh[(size_t)(w0 + m)*CHID + ju] =
            __bfloat162float(hHi[m*CR_HS + ju]) + __bfloat162float(hLo[m*CR_HS + ju]);
    }
}

// ---------------- persistent word GRU ----------------
__device__ __forceinline__ void grid_barrier() {
    __threadfence();
    __syncthreads();
    if (threadIdx.x == 0) {
        volatile unsigned int* vph = &g_barPhase;
        unsigned int ph = *vph;
        unsigned int a = atomicAdd(&g_barArrive, 1u);
        if (a == NBLK_W - 1u) {
            g_barArrive = 0u;
            __threadfence();
            *vph = ph + 1u;
        } else {
            while (*vph == ph) { __nanosleep(20); }
        }
        __threadfence();
    }
    __syncthreads();
}

__device__ __forceinline__ float dot4(float4 a, float4 b, float c) {
    c = fmaf(a.x, b.x, c); c = fmaf(a.y, b.y, c);
    c = fmaf(a.z, b.z, c); c = fmaf(a.w, b.w, c);
    return c;
}

#define WBB 32
#define WJB 16
#define WST 516

__global__ __launch_bounds__(128, 1)
void k_wordgru(const float* __restrict__ gWh, const float* __restrict__ gbh) {
    extern __shared__ float sm[];
    float* sW = sm;
    float* sH = sm + 48*WST;
    const int tid = threadIdx.x;
    const int bid = blockIdx.x;
    const int jc = bid & 31, bc = bid >> 5;
    const int j0 = jc * WJB, b0 = bc * WBB;
    const int jl = tid & 15;
    const int bq = tid >> 4;
    const int bl0 = bq * 4;

    for (int i = tid; i < 48*HID; i += 128) {
        int gl = i >> 9, k = i & 511;
        int gate = gl >> 4, jj = gl & 15;
        int g = gate*HID + j0 + jj;
        sW[gl*WST + k] = gWh[(size_t)g*HID + k];
    }
    const float bhR = gbh[j0 + jl];
    const float bhZ = gbh[HID + j0 + jl];
    const float bhN = gbh[2*HID + j0 + jl];
    {
        float4 z4 = make_float4(0.f,0.f,0.f,0.f);
        float4* h4 = (float4*)sH;
        for (int i = tid; i < WBB*HID/4; i += 128) h4[i] = z4;
    }
    __syncthreads();

    const float4* wR = (const float4*)(sW + (0*16 + jl)*WST);
    const float4* wZ = (const float4*)(sW + (16  + jl)*WST);
    const float4* wN = (const float4*)(sW + (32  + jl)*WST);
    const int j = j0 + jl;

    for (int s = 0; s < SSQ; s++) {
        float xr[4], xz[4], xn[4];
        #pragma unroll
        for (int q = 0; q < 4; q++) {
            size_t base = ((size_t)(b0 + bl0 + q)*SSQ + s) * G3H;
            xr[q] = g_xw[base + j];
            xz[q] = g_xw[base + HID + j];
            xn[q] = g_xw[base + 2*HID + j];
        }

        float aR[4], aZ[4], aNh[4];
        #pragma unroll
        for (int q = 0; q < 4; q++) { aR[q]=bhR; aZ[q]=bhZ; aNh[q]=bhN; }

        const float4* h0p = (const float4*)(sH + (bl0+0)*HID);
        const float4* h1p = (const float4*)(sH + (bl0+1)*HID);
        const float4* h2p = (const float4*)(sH + (bl0+2)*HID);
        const float4* h3p = (const float4*)(sH + (bl0+3)*HID);
        #pragma unroll 4
        for (int k4 = 0; k4 < HID/4; k4++) {
            float4 r4 = wR[k4], z4 = wZ[k4], n4 = wN[k4];
            float4 h0 = h0p[k4], h1 = h1p[k4], h2 = h2p[k4], h3 = h3p[k4];
            aR[0]=dot4(h0,r4,aR[0]); aZ[0]=dot4(h0,z4,aZ[0]); aNh[0]=dot4(h0,n4,aNh[0]);
            aR[1]=dot4(h1,r4,aR[1]); aZ[1]=dot4(h1,z4,aZ[1]); aNh[1]=dot4(h1,n4,aNh[1]);
            aR[2]=dot4(h2,r4,aR[2]); aZ[2]=dot4(h2,z4,aZ[2]); aNh[2]=dot4(h2,n4,aNh[2]);
            aR[3]=dot4(h3,r4,aR[3]); aZ[3]=dot4(h3,z4,aZ[3]); aNh[3]=dot4(h3,n4,aNh[3]);
        }

        float* hOut = g_hword + ((s + 1) & 1) * (BB*HID);
        #pragma unroll
        for (int q = 0; q < 4; q++) {
            int b = b0 + bl0 + q;
            float r  = 1.f / (1.f + expf(-(xr[q] + aR[q])));
            float z  = 1.f / (1.f + expf(-(xz[q] + aZ[q])));
            float nn = tanhf(xn[q] + r*aNh[q]);
            float hp = sH[(bl0+q)*HID + j];
            float hn = nn + z*(hp - nn);
            hOut[b*HID + j] = hn;
            g_gruout[((size_t)b*SSQ + s)*HID + j] = hn;
        }
        if (s == SSQ - 1) break;
        grid_barrier();
        const float4* hIn4 = (const float4*)(g_hword + ((s + 1) & 1) * (BB*HID) + b0*HID);
        float4* sH4 = (float4*)sH;
        for (int i = tid; i < WBB*HID/4; i += 128) sH4[i] = hIn4[i];
        __syncthreads();
    }
}

// ---------------- classifier ----------------
__global__ __launch_bounds__(256)
void k_cls(const float* __restrict__ clsW, const float* __restrict__ clsb,
           float* __restrict__ out) {
    const int warp = threadIdx.x >> 5, lane = threadIdx.x & 31;
    const int gw = blockIdx.x * 8 + warp;
    for (int row = gw; row < NW; row += gridDim.x * 8) {
        const float* hrow = g_gruout + (size_t)row * HID;
        float acc[NCLS];
        #pragma unroll
        for (int c = 0; c < NCLS; c++) acc[c] = 0.f;
        for (int k = lane; k < HID; k += 32) {
            float hv = hrow[k];
            #pragma unroll
            for (int c = 0; c < NCLS; c++)
                acc[c] = fmaf(hv, clsW[c*HID + k], acc[c]);
        }
        #pragma unroll
        for (int off = 16; off > 0; off >>= 1) {
            #pragma unroll
            for (int c = 0; c < NCLS; c++)
                acc[c] += __shfl_down_sync(0xffffffffu, acc[c], off);
        }
        if (lane == 0) {
            #pragma unroll
            for (int c = 0; c < NCLS; c++)
                out[(size_t)row*NCLS + c] = acc[c] + clsb[c];
        }
    }
}

// ---------------- launch ----------------
extern "C" void kernel_launch(void* const* d_in, const int* in_sizes, int n_in,
                              void* d_out, int out_size) {
    const int*   x     = (const int*)  d_in[0];
    const int*   xch   = (const int*)  d_in[1];
    const float* embw  = (const float*)d_in[2];
    const float* cembw = (const float*)d_in[3];
    const float* cWi   = (const float*)d_in[4];
    const float* cWh   = (const float*)d_in[5];
    const float* cbi   = (const float*)d_in[6];
    const float* cbh   = (const float*)d_in[7];
    const float* gWi   = (const float*)d_in[8];
    const float* gWh   = (const float*)d_in[9];
    const float* gbi   = (const float*)d_in[10];
    const float* gbh   = (const float*)d_in[11];
    const float* clsW  = (const float*)d_in[12];
    const float* clsb  = (const float*)d_in[13];
    float* out = (float*)d_out;

    void *aCh, *aCl, *aXh, *aXl, *bCh, *bCl, *bXh, *bXl;
    cudaGetSymbolAddress(&aCh, g_AcH);  cudaGetSymbolAddress(&aCl, g_AcL);
    cudaGetSymbolAddress(&aXh, g_AxH);  cudaGetSymbolAddress(&aXl, g_AxL);
    cudaGetSymbolAddress(&bCh, g_BcxHi); cudaGetSymbolAddress(&bCl, g_BcxLo);
    cudaGetSymbolAddress(&bXh, g_BxwHi); cudaGetSymbolAddress(&bXl, g_BxwLo);
    void *pcxw, *pxw;
    cudaGetSymbolAddress(&pcxw, g_cxw);
    cudaGetSymbolAddress(&pxw, g_xw);

    const int wsmem  = (48*WST + WBB*HID) * 4;
    cudaFuncSetAttribute(k_charrec, cudaFuncAttributeMaxDynamicSharedMemorySize, CR_SMEM);
    cudaFuncSetAttribute(k_wordgru, cudaFuncAttributeMaxDynamicSharedMemorySize, wsmem);
    cudaFuncSetAttribute(k_gemm,    cudaFuncAttributeMaxDynamicSharedMemorySize, GEMM_SMEM);

    k_prep<<<512, 256>>>(cWh, gWi, cWi);
    k_gatherA_c<<<NW*LLC/256, 256>>>(xch, cembw);
    dim3 gc(G3C/64, NW*LLC/128);   // (6, 4096)
    k_gemm<<<gc, 256, GEMM_SMEM>>>((const __nv_bfloat16*)aCh, (const __nv_bfloat16*)aCl,
                                   (const __nv_bfloat16*)bCh, (const __nv_bfloat16*)bCl,
                                   cbi, (float*)pcxw, G3C, CEMB);
    k_charrec<<<NW/CRM, 512, CR_SMEM>>>(cbh);
    k_gatherA_x<<<NW/8, 256>>>(x, embw);
    dim3 gx(G3H/64, NW/128);       // (24, 256)
    k_gemm<<<gx, 256, GEMM_SMEM>>>((const __nv_bfloat16*)aXh, (const __nv_bfloat16*)aXl,
                                   (const __nv_bfloat16*)bXh, (const __nv_bfloat16*)bXl,
                                   gbi, (float*)pxw, G3H, DIM);
    k_wordgru<<<NBLK_W, 128, wsmem>>>(gWh, gbh);
    k_cls<<<512, 256>>>(clsW, clsb, out);
}